// round 7
// baseline (speedup 1.0000x reference)
#include <cuda_runtime.h>
#include <cstdint>
#include <math.h>

#define BB 512
#define DD 2048
#define KK 128
#define PP 5
#define NN (KK * PP)      // 640
#define OUTW (DD + KK)    // 2176

#define SPLIT 8
#define KC (DD / SPLIT)   // 256 K per CTA
#define TM 64
#define TN 160
#define ROWP 36           // padded row stride (floats): 16B-aligned for cp.async
#define B_OFF (TM * ROWP)             // 2304 floats
#define STG_FLOATS ((TM + TN) * ROWP) // 8064 floats = 32256 B
#define NSTAGE 3
#define GEMM_SMEM (NSTAGE * STG_FLOATS * 4)  // 96768 B -> 2 CTAs/SM

// ---------------- scratch (no cudaMalloc allowed) ----------------
__device__ float g_part[SPLIT * BB * NN];  // K-split partial actv (x log2e folded)
__device__ float g_scale[NN];
__device__ float g_xr[BB * DD];            // x rounded to tf32, k-permuted
__device__ float g_bt[NN * DD];            // theta^T * scale * log2e, tf32, k-permuted

__device__ __forceinline__ float rna_tf32(float v) {
    uint32_t u;
    asm("cvt.rna.tf32.f32 %0, %1;" : "=r"(u) : "f"(v));
    return __uint_as_float(u);
}
__device__ __forceinline__ uint32_t s2u(const void* p) {
    uint32_t a;
    asm("{ .reg .u64 t; cvta.to.shared.u64 t, %1; cvt.u32.u64 %0, t; }"
        : "=r"(a) : "l"(p));
    return a;
}

// ---------------------------------------------------------------------------
// 1) column scales: scale[kp] = exp(lws)/||theta[:,kp]|| * log2(e)
// ---------------------------------------------------------------------------
__global__ void scale_kernel(const float* __restrict__ theta,
                             const float* __restrict__ lws) {
    int c = threadIdx.x & 31;
    int q = threadIdx.x >> 5;
    int col = blockIdx.x * 32 + c;
    float s = 0.f;
    for (int d = q; d < DD; d += 8) {
        float v = theta[d * NN + col];
        s += v * v;
    }
    __shared__ float red[8][32];
    red[q][c] = s;
    __syncthreads();
    if (q == 0) {
        float t = 0.f;
#pragma unroll
        for (int i = 0; i < 8; i++) t += red[i][c];
        g_scale[col] = __expf(lws[col]) * rsqrtf(t) * 1.4426950408889634f;
    }
}

// ---------------------------------------------------------------------------
// 2a) round x -> g_xr (tf32 rna, k-permuted within 8-groups: pos=2*(k&3)+(k>>2)),
//     AND copy raw x -> out[:, 0:2048] (fused)
// ---------------------------------------------------------------------------
__global__ void round_x_kernel(const float* __restrict__ x, float* __restrict__ out) {
    int n8 = BB * DD / 8;
    for (int i = blockIdx.x * blockDim.x + threadIdx.x; i < n8;
         i += gridDim.x * blockDim.x) {
        int row = i >> 8;              // 256 8-col groups per row
        int g = i & 255;
        const float4* p = (const float4*)(x + (size_t)row * DD + g * 8);
        float4 lo = p[0], hi = p[1];
        float4* o = (float4*)(out + (size_t)row * OUTW + g * 8);
        o[0] = lo; o[1] = hi;          // raw copy
        // permuted order: k0,k4,k1,k5 | k2,k6,k3,k7
        float4 q0 = make_float4(rna_tf32(lo.x), rna_tf32(hi.x),
                                rna_tf32(lo.y), rna_tf32(hi.y));
        float4 q1 = make_float4(rna_tf32(lo.z), rna_tf32(hi.z),
                                rna_tf32(lo.w), rna_tf32(hi.w));
        float4* q = (float4*)(g_xr + (size_t)row * DD + g * 8);
        q[0] = q0; q[1] = q1;
    }
}

// ---------------------------------------------------------------------------
// 2b) transpose theta [2048,640] -> g_bt [640,2048], fold scale, tf32, k-permuted
// ---------------------------------------------------------------------------
__global__ void transpose_kernel(const float* __restrict__ theta) {
    __shared__ float t[32][33];
    int n0 = blockIdx.x * 32, d0 = blockIdx.y * 32;
    int tx = threadIdx.x, ty = threadIdx.y;
    float sc = g_scale[n0 + tx];
#pragma unroll
    for (int i = 0; i < 4; i++) {
        int r = ty + i * 8;
        t[r][tx] = theta[(size_t)(d0 + r) * NN + n0 + tx] * sc;
    }
    __syncthreads();
    int txp = (tx & ~7) | (((tx & 3) << 1) | ((tx >> 2) & 1));  // k-perm
#pragma unroll
    for (int i = 0; i < 4; i++) {
        int r = ty + i * 8;
        g_bt[(size_t)(n0 + r) * DD + d0 + txp] = rna_tf32(t[tx][r]);
    }
}

// ---------------------------------------------------------------------------
// 3) tf32 mma.sync GEMM, cp.async 3-stage ring, 2 CTAs/SM.
//    CTA: 64m x 160n x KC=256 (split over blockIdx.z, SPLIT=8). 256 thr, 8 warps.
//    Warp grid 2m x 4n, warp tile 32x40. K-permuted smem -> LDS.64 frag loads.
//    grid (4, 8, 8) = 256 CTAs.
// ---------------------------------------------------------------------------
__device__ __forceinline__ void mma_tf32(float* c,
                                         float a0, float a1, float a2, float a3,
                                         float b0, float b1) {
    asm volatile(
        "mma.sync.aligned.m16n8k8.row.col.f32.tf32.tf32.f32 "
        "{%0,%1,%2,%3}, {%4,%5,%6,%7}, {%8,%9}, {%0,%1,%2,%3};"
        : "+f"(c[0]), "+f"(c[1]), "+f"(c[2]), "+f"(c[3])
        : "r"(__float_as_uint(a0)), "r"(__float_as_uint(a1)),
          "r"(__float_as_uint(a2)), "r"(__float_as_uint(a3)),
          "r"(__float_as_uint(b0)), "r"(__float_as_uint(b1)));
}

__global__ __launch_bounds__(256, 2) void gemm_mma_kernel() {
    extern __shared__ float sm[];
    const int tid = threadIdx.x, lane = tid & 31, wid = tid >> 5;
    const int wm = wid & 1;        // m warp (32 rows)
    const int wn = wid >> 1;       // n warp (40 cols)
    const int mBase = blockIdx.y * TM;
    const int nBase = blockIdx.x * TN;
    const size_t kbase0 = (size_t)blockIdx.z * KC;

    // ---- producer setup: 7 cp.async(16B) chunks per thread per stage ----
    size_t srcg[7];
    uint32_t dsts[7];
    const uint32_t sb = s2u(sm);
#pragma unroll
    for (int q = 0; q < 7; q++) {
        int c = tid + q * 256;                 // 0..1791
        const float* src;
        uint32_t d;
        if (c < 512) {                          // A: 64 rows x 8 chunks
            int r = c >> 3, p = c & 7;
            src = g_xr + (size_t)(mBase + r) * DD + kbase0 + p * 4;
            d = (uint32_t)(r * ROWP + p * 4) * 4;
        } else {                                // B: 160 rows x 8 chunks
            int cb = c - 512;
            int n = cb >> 3, p = cb & 7;
            src = g_bt + (size_t)(nBase + n) * DD + kbase0 + p * 4;
            d = (uint32_t)(B_OFF + n * ROWP + p * 4) * 4;
        }
        srcg[q] = __cvta_generic_to_global(src);
        dsts[q] = sb + d;
    }

#define LOAD_STAGE(it_) do {                                               \
    uint32_t soff_ = (uint32_t)(((it_) % 3) * (STG_FLOATS * 4));           \
    size_t go_ = (size_t)(it_) * 128;                                      \
    _Pragma("unroll")                                                      \
    for (int q_ = 0; q_ < 7; q_++)                                         \
        asm volatile("cp.async.cg.shared.global [%0], [%1], 16;"           \
                     :: "r"(dsts[q_] + soff_), "l"(srcg[q_] + go_));       \
    asm volatile("cp.async.commit_group;" ::: "memory");                   \
} while (0)

    LOAD_STAGE(0);
    LOAD_STAGE(1);

    float acc[5][2][4] = {};
    const int aRow = wm * 32 + (lane >> 2);
    const int kCol = lane & 3;
    const int bRow = wn * 40 + (lane >> 2);

    const int NIT = KC / 32;   // 8
#pragma unroll 1
    for (int it = 0; it < NIT; ++it) {
        asm volatile("cp.async.wait_group 1;" ::: "memory");
        __syncthreads();                        // single barrier per iter
        if (it + 2 < NIT) LOAD_STAGE(it + 2);
        else asm volatile("cp.async.commit_group;" ::: "memory");

        const float* s = sm + (it % 3) * STG_FLOATS;
#pragma unroll
        for (int ks = 0; ks < 4; ++ks) {
            float a[2][4];
#pragma unroll
            for (int ms = 0; ms < 2; ++ms) {
                const float* ap = s + (aRow + ms * 16) * ROWP + ks * 8 + kCol * 2;
                float2 lo = *(const float2*)ap;              // (r,k) (r,k+4)
                float2 hi = *(const float2*)(ap + 8 * ROWP); // (r+8,k) (r+8,k+4)
                a[ms][0] = lo.x; a[ms][1] = hi.x;
                a[ms][2] = lo.y; a[ms][3] = hi.y;
            }
#pragma unroll
            for (int nb = 0; nb < 5; ++nb) {
                float2 b = *(const float2*)(s + B_OFF +
                            (bRow + nb * 8) * ROWP + ks * 8 + kCol * 2);
                mma_tf32(acc[nb][0], a[0][0], a[0][1], a[0][2], a[0][3], b.x, b.y);
                mma_tf32(acc[nb][1], a[1][0], a[1][1], a[1][2], a[1][3], b.x, b.y);
            }
        }
    }

    // ---- epilogue: write K-split partials ----
    float* op = g_part + (size_t)blockIdx.z * BB * NN;
    const int row0 = mBase + wm * 32 + (lane >> 2);
    const int col0 = nBase + wn * 40 + (lane & 3) * 2;
#pragma unroll
    for (int nb = 0; nb < 5; ++nb) {
#pragma unroll
        for (int ms = 0; ms < 2; ++ms) {
            int row = row0 + ms * 16;
            int col = col0 + nb * 8;
            *(float2*)&op[(size_t)row * NN + col] =
                make_float2(acc[nb][ms][0], acc[nb][ms][1]);
            *(float2*)&op[(size_t)(row + 8) * NN + col] =
                make_float2(acc[nb][ms][2], acc[nb][ms][3]);
        }
    }
#undef LOAD_STAGE
}

// ---------------------------------------------------------------------------
// 4) pairwise, min-trick:
//    sum_p |a_i - a_j| = Si + Sj - 2*M,  M = sum_p min(a_ip, a_jp)
//    f = exp2(-Si) * sum_j exp2(2M - Sj) - 1 + bias   (a prescaled by log2 e)
// ---------------------------------------------------------------------------
__global__ __launch_bounds__(512, 1)
void pairwise_kernel(const float* __restrict__ bias, float* __restrict__ out) {
    int k = blockIdx.x;
    int i = threadIdx.x;
    __shared__ float sA[BB][8];

    float a0 = 0.f, a1 = 0.f, a2 = 0.f, a3 = 0.f, a4 = 0.f;
#pragma unroll
    for (int s = 0; s < SPLIT; s++) {
        const float* p = g_part + (size_t)s * BB * NN + (size_t)i * NN + k * PP;
        a0 += p[0]; a1 += p[1]; a2 += p[2]; a3 += p[3]; a4 += p[4];
    }
    float Si = ((a0 + a1) + (a2 + a3)) + a4;
    sA[i][0] = a0; sA[i][1] = a1; sA[i][2] = a2; sA[i][3] = a3;
    sA[i][4] = a4; sA[i][5] = Si;
    __syncthreads();

    float acc = 0.f;
#pragma unroll 8
    for (int j = 0; j < BB; j++) {
        float4 v = *(const float4*)&sA[j][0];
        float2 w = *(const float2*)&sA[j][4];      // m4, Sj
        float m0 = fminf(a0, v.x);
        float m1 = fminf(a1, v.y);
        float m2 = fminf(a2, v.z);
        float m3 = fminf(a3, v.w);
        float m4 = fminf(a4, w.x);
        float M = ((m0 + m1) + (m2 + m3)) + m4;
        float arg = fmaf(2.0f, M, -w.y);           // 2M - Sj
        float e;
        asm("ex2.approx.ftz.f32 %0, %1;" : "=f"(e) : "f"(arg));
        acc += e;
    }
    float si_scale;
    asm("ex2.approx.ftz.f32 %0, %1;" : "=f"(si_scale) : "f"(-Si));
    out[(size_t)i * OUTW + DD + k] = fmaf(acc, si_scale, bias[k] - 1.0f);
}

// ---------------------------------------------------------------------------
extern "C" void kernel_launch(void* const* d_in, const int* in_sizes, int n_in,
                              void* d_out, int out_size) {
    const float* x     = (const float*)d_in[0];   // [512, 2048]
    const float* theta = (const float*)d_in[1];   // [2048, 128, 5]
    const float* lws   = (const float*)d_in[2];   // [128, 5]
    const float* bias  = (const float*)d_in[3];   // [128]
    float* out = (float*)d_out;                   // [512, 2176]

    cudaFuncSetAttribute(gemm_mma_kernel,
                         cudaFuncAttributeMaxDynamicSharedMemorySize, GEMM_SMEM);

    scale_kernel<<<20, 256>>>(theta, lws);
    round_x_kernel<<<256, 256>>>(x, out);
    transpose_kernel<<<dim3(NN / 32, DD / 32), dim3(32, 8)>>>(theta);
    gemm_mma_kernel<<<dim3(NN / TN, BB / TM, SPLIT), 256, GEMM_SMEM>>>();
    pairwise_kernel<<<KK, BB>>>(bias, out);
}

// round 8
// speedup vs baseline: 1.0250x; 1.0250x over previous
#include <cuda_runtime.h>
#include <cstdint>
#include <math.h>

#define BB 512
#define DD 2048
#define KK 128
#define PP 5
#define NN (KK * PP)      // 640
#define OUTW (DD + KK)    // 2176

#define SPLIT 4
#define KC (DD / SPLIT)   // 512 K per CTA
#define TM 64
#define TN 160
#define ROWP 36           // padded row stride (floats): 16B-aligned for cp.async
#define B_OFF (TM * ROWP)             // 2304 floats
#define STG_FLOATS ((TM + TN) * ROWP) // 8064 floats = 32256 B
#define NSTAGE 4
#define GEMM_SMEM (NSTAGE * STG_FLOATS * 4)  // 129024 B -> 1 CTA/SM

// ---------------- scratch (no cudaMalloc allowed) ----------------
__device__ float g_part[SPLIT * BB * NN];  // K-split partial actv (x log2e folded)
__device__ float g_scale[NN];
__device__ float g_xr[BB * DD];            // x rounded to tf32, k-permuted
__device__ float g_bt[NN * DD];            // theta^T * scale * log2e, tf32, k-permuted
__device__ float g_fh[2 * BB * KK];        // pairwise half-sums [jhalf][i][k]

__device__ __forceinline__ float rna_tf32(float v) {
    uint32_t u;
    asm("cvt.rna.tf32.f32 %0, %1;" : "=r"(u) : "f"(v));
    return __uint_as_float(u);
}
__device__ __forceinline__ uint32_t s2u(const void* p) {
    uint32_t a;
    asm("{ .reg .u64 t; cvta.to.shared.u64 t, %1; cvt.u32.u64 %0, t; }"
        : "=r"(a) : "l"(p));
    return a;
}

// ---------------------------------------------------------------------------
// 1) column scales: scale[kp] = exp(lws)/||theta[:,kp]|| * log2(e)
// ---------------------------------------------------------------------------
__global__ void scale_kernel(const float* __restrict__ theta,
                             const float* __restrict__ lws) {
    int c = threadIdx.x & 31;
    int q = threadIdx.x >> 5;
    int col = blockIdx.x * 32 + c;
    float s = 0.f;
    for (int d = q; d < DD; d += 8) {
        float v = theta[d * NN + col];
        s += v * v;
    }
    __shared__ float red[8][32];
    red[q][c] = s;
    __syncthreads();
    if (q == 0) {
        float t = 0.f;
#pragma unroll
        for (int i = 0; i < 8; i++) t += red[i][c];
        g_scale[col] = __expf(lws[col]) * rsqrtf(t) * 1.4426950408889634f;
    }
}

// ---------------------------------------------------------------------------
// 2a) round x -> g_xr (tf32 rna, k-permuted within 8-groups: pos=2*(k&3)+(k>>2)),
//     AND copy raw x -> out[:, 0:2048] (fused)
// ---------------------------------------------------------------------------
__global__ void round_x_kernel(const float* __restrict__ x, float* __restrict__ out) {
    int n8 = BB * DD / 8;
    for (int i = blockIdx.x * blockDim.x + threadIdx.x; i < n8;
         i += gridDim.x * blockDim.x) {
        int row = i >> 8;
        int g = i & 255;
        const float4* p = (const float4*)(x + (size_t)row * DD + g * 8);
        float4 lo = p[0], hi = p[1];
        float4* o = (float4*)(out + (size_t)row * OUTW + g * 8);
        o[0] = lo; o[1] = hi;          // raw copy
        // permuted order: k0,k4,k1,k5 | k2,k6,k3,k7
        float4 q0 = make_float4(rna_tf32(lo.x), rna_tf32(hi.x),
                                rna_tf32(lo.y), rna_tf32(hi.y));
        float4 q1 = make_float4(rna_tf32(lo.z), rna_tf32(hi.z),
                                rna_tf32(lo.w), rna_tf32(hi.w));
        float4* q = (float4*)(g_xr + (size_t)row * DD + g * 8);
        q[0] = q0; q[1] = q1;
    }
}

// ---------------------------------------------------------------------------
// 2b) transpose theta [2048,640] -> g_bt [640,2048], fold scale, tf32, k-permuted
// ---------------------------------------------------------------------------
__global__ void transpose_kernel(const float* __restrict__ theta) {
    __shared__ float t[32][33];
    int n0 = blockIdx.x * 32, d0 = blockIdx.y * 32;
    int tx = threadIdx.x, ty = threadIdx.y;
    float sc = g_scale[n0 + tx];
#pragma unroll
    for (int i = 0; i < 4; i++) {
        int r = ty + i * 8;
        t[r][tx] = theta[(size_t)(d0 + r) * NN + n0 + tx] * sc;
    }
    __syncthreads();
    int txp = (tx & ~7) | (((tx & 3) << 1) | ((tx >> 2) & 1));  // k-perm
#pragma unroll
    for (int i = 0; i < 4; i++) {
        int r = ty + i * 8;
        g_bt[(size_t)(n0 + r) * DD + d0 + txp] = rna_tf32(t[tx][r]);
    }
}

// ---------------------------------------------------------------------------
// 3) tf32 mma.sync GEMM, cp.async 4-stage ring, 1 CTA/SM (R6 config + LDS.64 perm).
//    CTA: 64m x 160n x KC=512 (split over blockIdx.z, SPLIT=4). 256 thr, 8 warps.
//    grid (4, 8, 4) = 128 CTAs, one clean wave.
// ---------------------------------------------------------------------------
__device__ __forceinline__ void mma_tf32(float* c,
                                         float a0, float a1, float a2, float a3,
                                         float b0, float b1) {
    asm volatile(
        "mma.sync.aligned.m16n8k8.row.col.f32.tf32.tf32.f32 "
        "{%0,%1,%2,%3}, {%4,%5,%6,%7}, {%8,%9}, {%0,%1,%2,%3};"
        : "+f"(c[0]), "+f"(c[1]), "+f"(c[2]), "+f"(c[3])
        : "r"(__float_as_uint(a0)), "r"(__float_as_uint(a1)),
          "r"(__float_as_uint(a2)), "r"(__float_as_uint(a3)),
          "r"(__float_as_uint(b0)), "r"(__float_as_uint(b1)));
}

__global__ __launch_bounds__(256, 1) void gemm_mma_kernel() {
    extern __shared__ float sm[];
    const int tid = threadIdx.x, lane = tid & 31, wid = tid >> 5;
    const int wm = wid & 1;        // m warp (32 rows)
    const int wn = wid >> 1;       // n warp (40 cols)
    const int mBase = blockIdx.y * TM;
    const int nBase = blockIdx.x * TN;
    const size_t kbase0 = (size_t)blockIdx.z * KC;

    // ---- producer setup: 7 cp.async(16B) chunks per thread per stage ----
    size_t srcg[7];
    uint32_t dsts[7];
    const uint32_t sb = s2u(sm);
#pragma unroll
    for (int q = 0; q < 7; q++) {
        int c = tid + q * 256;                 // 0..1791
        const float* src;
        uint32_t d;
        if (c < 512) {                          // A: 64 rows x 8 chunks
            int r = c >> 3, p = c & 7;
            src = g_xr + (size_t)(mBase + r) * DD + kbase0 + p * 4;
            d = (uint32_t)(r * ROWP + p * 4) * 4;
        } else {                                // B: 160 rows x 8 chunks
            int cb = c - 512;
            int n = cb >> 3, p = cb & 7;
            src = g_bt + (size_t)(nBase + n) * DD + kbase0 + p * 4;
            d = (uint32_t)(B_OFF + n * ROWP + p * 4) * 4;
        }
        srcg[q] = __cvta_generic_to_global(src);
        dsts[q] = sb + d;
    }

#define LOAD_STAGE(it_) do {                                               \
    uint32_t soff_ = (uint32_t)(((it_) & 3) * (STG_FLOATS * 4));           \
    size_t go_ = (size_t)(it_) * 128;                                      \
    _Pragma("unroll")                                                      \
    for (int q_ = 0; q_ < 7; q_++)                                         \
        asm volatile("cp.async.cg.shared.global [%0], [%1], 16;"           \
                     :: "r"(dsts[q_] + soff_), "l"(srcg[q_] + go_));       \
    asm volatile("cp.async.commit_group;" ::: "memory");                   \
} while (0)

    LOAD_STAGE(0);
    LOAD_STAGE(1);
    LOAD_STAGE(2);

    float acc[5][2][4] = {};
    const int aRow = wm * 32 + (lane >> 2);
    const int kCol = lane & 3;
    const int bRow = wn * 40 + (lane >> 2);

    const int NIT = KC / 32;   // 16
#pragma unroll 1
    for (int it = 0; it < NIT; ++it) {
        asm volatile("cp.async.wait_group 2;" ::: "memory");
        __syncthreads();                        // single barrier per iter
        if (it + 3 < NIT) LOAD_STAGE(it + 3);
        else asm volatile("cp.async.commit_group;" ::: "memory");

        const float* s = sm + (it & 3) * STG_FLOATS;
#pragma unroll
        for (int ks = 0; ks < 4; ++ks) {
            float a[2][4];
#pragma unroll
            for (int ms = 0; ms < 2; ++ms) {
                const float* ap = s + (aRow + ms * 16) * ROWP + ks * 8 + kCol * 2;
                float2 lo = *(const float2*)ap;              // (r,k) (r,k+4)
                float2 hi = *(const float2*)(ap + 8 * ROWP); // (r+8,k) (r+8,k+4)
                a[ms][0] = lo.x; a[ms][1] = hi.x;
                a[ms][2] = lo.y; a[ms][3] = hi.y;
            }
#pragma unroll
            for (int nb = 0; nb < 5; ++nb) {
                float2 b = *(const float2*)(s + B_OFF +
                            (bRow + nb * 8) * ROWP + ks * 8 + kCol * 2);
                mma_tf32(acc[nb][0], a[0][0], a[0][1], a[0][2], a[0][3], b.x, b.y);
                mma_tf32(acc[nb][1], a[1][0], a[1][1], a[1][2], a[1][3], b.x, b.y);
            }
        }
    }

    // ---- epilogue: write K-split partials ----
    float* op = g_part + (size_t)blockIdx.z * BB * NN;
    const int row0 = mBase + wm * 32 + (lane >> 2);
    const int col0 = nBase + wn * 40 + (lane & 3) * 2;
#pragma unroll
    for (int nb = 0; nb < 5; ++nb) {
#pragma unroll
        for (int ms = 0; ms < 2; ++ms) {
            int row = row0 + ms * 16;
            int col = col0 + nb * 8;
            *(float2*)&op[(size_t)row * NN + col] =
                make_float2(acc[nb][ms][0], acc[nb][ms][1]);
            *(float2*)&op[(size_t)(row + 8) * NN + col] =
                make_float2(acc[nb][ms][2], acc[nb][ms][3]);
        }
    }
#undef LOAD_STAGE
}

// ---------------------------------------------------------------------------
// 4) pairwise, min-trick, 2 i-rows/thread, j split in halves:
//    s_ij = Si + Sj - 2M,  M = sum_p min(a_ip, a_jp)
//    half h = exp2(-Si) * sum_{j in half} exp2(2M - Sj)
//    smem stores 2a (so M2 = 2M comes out of the min-sum directly) and Sj.
//    grid (128 k, 2 jhalf), 256 threads (thread t -> i = t, t+256).
// ---------------------------------------------------------------------------
__global__ __launch_bounds__(256, 2)
void pairwise_kernel(const float* __restrict__ bias) {
    const int k = blockIdx.x;
    const int jh = blockIdx.y;
    const int t = threadIdx.x;
    __shared__ float sD[BB][8];    // 2a0..2a4, Sj

    float da[2][5], Si[2];
#pragma unroll
    for (int r = 0; r < 2; r++) {
        int i = t + r * 256;
        float a0 = 0.f, a1 = 0.f, a2 = 0.f, a3 = 0.f, a4 = 0.f;
#pragma unroll
        for (int s = 0; s < SPLIT; s++) {
            const float* p = g_part + (size_t)s * BB * NN + (size_t)i * NN + k * PP;
            a0 += p[0]; a1 += p[1]; a2 += p[2]; a3 += p[3]; a4 += p[4];
        }
        Si[r] = ((a0 + a1) + (a2 + a3)) + a4;
        da[r][0] = a0 + a0; da[r][1] = a1 + a1; da[r][2] = a2 + a2;
        da[r][3] = a3 + a3; da[r][4] = a4 + a4;
        sD[i][0] = da[r][0]; sD[i][1] = da[r][1]; sD[i][2] = da[r][2];
        sD[i][3] = da[r][3]; sD[i][4] = da[r][4]; sD[i][5] = Si[r];
    }
    __syncthreads();

    float acc0 = 0.f, acc1 = 0.f;
    const int j0 = jh * 256;
#pragma unroll 4
    for (int jj = 0; jj < 256; jj++) {
        int j = j0 + jj;
        float4 v = *(const float4*)&sD[j][0];     // 2a0..2a3
        float2 w = *(const float2*)&sD[j][4];     // 2a4, Sj
        // i0
        float m0 = fminf(da[0][0], v.x), m1 = fminf(da[0][1], v.y);
        float m2 = fminf(da[0][2], v.z), m3 = fminf(da[0][3], v.w);
        float m4 = fminf(da[0][4], w.x);
        float arg0 = ((m0 + m1) + (m2 + m3)) + (m4 - w.y);   // 2M - Sj
        float e0;
        asm("ex2.approx.ftz.f32 %0, %1;" : "=f"(e0) : "f"(arg0));
        acc0 += e0;
        // i1
        float n0 = fminf(da[1][0], v.x), n1 = fminf(da[1][1], v.y);
        float n2 = fminf(da[1][2], v.z), n3 = fminf(da[1][3], v.w);
        float n4 = fminf(da[1][4], w.x);
        float arg1 = ((n0 + n1) + (n2 + n3)) + (n4 - w.y);
        float e1;
        asm("ex2.approx.ftz.f32 %0, %1;" : "=f"(e1) : "f"(arg1));
        acc1 += e1;
    }
    float sc0, sc1;
    asm("ex2.approx.ftz.f32 %0, %1;" : "=f"(sc0) : "f"(-Si[0]));
    asm("ex2.approx.ftz.f32 %0, %1;" : "=f"(sc1) : "f"(-Si[1]));
    float* dst = g_fh + (size_t)jh * BB * KK;
    dst[(size_t)t * KK + k] = acc0 * sc0;
    dst[(size_t)(t + 256) * KK + k] = acc1 * sc1;
}

// ---------------------------------------------------------------------------
// 5) finish: out[i, D+k] = h0 + h1 - 1 + bias[k]
// ---------------------------------------------------------------------------
__global__ void finish_kernel(const float* __restrict__ bias, float* __restrict__ out) {
    int idx = blockIdx.x * blockDim.x + threadIdx.x;   // 65536
    int i = idx >> 7;
    int k = idx & 127;
    out[(size_t)i * OUTW + DD + k] =
        g_fh[idx] + g_fh[BB * KK + idx] - 1.0f + bias[k];
}

// ---------------------------------------------------------------------------
extern "C" void kernel_launch(void* const* d_in, const int* in_sizes, int n_in,
                              void* d_out, int out_size) {
    const float* x     = (const float*)d_in[0];   // [512, 2048]
    const float* theta = (const float*)d_in[1];   // [2048, 128, 5]
    const float* lws   = (const float*)d_in[2];   // [128, 5]
    const float* bias  = (const float*)d_in[3];   // [128]
    float* out = (float*)d_out;                   // [512, 2176]

    cudaFuncSetAttribute(gemm_mma_kernel,
                         cudaFuncAttributeMaxDynamicSharedMemorySize, GEMM_SMEM);

    scale_kernel<<<20, 256>>>(theta, lws);
    round_x_kernel<<<256, 256>>>(x, out);
    transpose_kernel<<<dim3(NN / 32, DD / 32), dim3(32, 8)>>>(theta);
    gemm_mma_kernel<<<dim3(NN / TN, BB / TM, SPLIT), 256, GEMM_SMEM>>>();
    pairwise_kernel<<<dim3(KK, 2), 256>>>(bias);
    finish_kernel<<<BB * KK / 256, 256>>>(bias, out);
}

// round 9
// speedup vs baseline: 1.1427x; 1.1148x over previous
#include <cuda_runtime.h>
#include <cstdint>
#include <math.h>

#define BB 512
#define DD 2048
#define KK 128
#define PP 5
#define NN (KK * PP)      // 640
#define OUTW (DD + KK)    // 2176

#define SPLIT 4
#define KC (DD / SPLIT)   // 512 K per CTA
#define TM 64
#define TN 160
#define ROWP 36           // padded row stride (floats): conflict-free LDS.32 + 16B-aligned
#define B_OFF (TM * ROWP)             // 2304 floats
#define STG_FLOATS ((TM + TN) * ROWP) // 8064 floats = 32256 B
#define NSTAGE 4
#define GEMM_SMEM (NSTAGE * STG_FLOATS * 4)  // 129024 B

// ---------------- scratch (no cudaMalloc allowed) ----------------
__device__ float g_part[SPLIT * BB * NN];  // K-split partial actv (x log2e folded)
__device__ float g_scale[NN];
__device__ float g_xr[BB * DD];            // x rounded to tf32 (rna)
__device__ float g_bt[NN * DD];            // theta^T * scale * log2e, tf32

__device__ __forceinline__ float rna_tf32(float v) {
    uint32_t u;
    asm("cvt.rna.tf32.f32 %0, %1;" : "=r"(u) : "f"(v));
    return __uint_as_float(u);
}
__device__ __forceinline__ uint32_t s2u(const void* p) {
    uint32_t a;
    asm("{ .reg .u64 t; cvta.to.shared.u64 t, %1; cvt.u32.u64 %0, t; }"
        : "=r"(a) : "l"(p));
    return a;
}

// ---------------------------------------------------------------------------
// 1) column scales: scale[kp] = exp(lws)/||theta[:,kp]|| * log2(e)
// ---------------------------------------------------------------------------
__global__ void scale_kernel(const float* __restrict__ theta,
                             const float* __restrict__ lws) {
    int c = threadIdx.x & 31;
    int q = threadIdx.x >> 5;
    int col = blockIdx.x * 32 + c;
    float s = 0.f;
    for (int d = q; d < DD; d += 8) {
        float v = theta[d * NN + col];
        s += v * v;
    }
    __shared__ float red[8][32];
    red[q][c] = s;
    __syncthreads();
    if (q == 0) {
        float t = 0.f;
#pragma unroll
        for (int i = 0; i < 8; i++) t += red[i][c];
        g_scale[col] = __expf(lws[col]) * rsqrtf(t) * 1.4426950408889634f;
    }
}

// ---------------------------------------------------------------------------
// 2a) round x -> g_xr (tf32 rna), AND copy raw x -> out[:, 0:2048] (fused)
// ---------------------------------------------------------------------------
__global__ void round_x_kernel(const float* __restrict__ x, float* __restrict__ out) {
    const float4* xi = (const float4*)x;
    float4* xo = (float4*)g_xr;
    int n4 = BB * DD / 4;
    for (int i = blockIdx.x * blockDim.x + threadIdx.x; i < n4;
         i += gridDim.x * blockDim.x) {
        float4 v = xi[i];
        int row = i >> 9;
        int c4 = i & 511;
        *(float4*)&out[(size_t)row * OUTW + c4 * 4] = v;   // raw copy
        v.x = rna_tf32(v.x); v.y = rna_tf32(v.y);
        v.z = rna_tf32(v.z); v.w = rna_tf32(v.w);
        xo[i] = v;
    }
}

// ---------------------------------------------------------------------------
// 2b) transpose theta [2048,640] -> g_bt [640,2048], fold scale, round to tf32
// ---------------------------------------------------------------------------
__global__ void transpose_kernel(const float* __restrict__ theta) {
    __shared__ float t[32][33];
    int n0 = blockIdx.x * 32, d0 = blockIdx.y * 32;
    int tx = threadIdx.x, ty = threadIdx.y;
    float sc = g_scale[n0 + tx];
#pragma unroll
    for (int i = 0; i < 4; i++) {
        int r = ty + i * 8;
        t[r][tx] = theta[(size_t)(d0 + r) * NN + n0 + tx] * sc;
    }
    __syncthreads();
#pragma unroll
    for (int i = 0; i < 4; i++) {
        int r = ty + i * 8;
        g_bt[(size_t)(n0 + r) * DD + d0 + tx] = rna_tf32(t[tx][r]);
    }
}

// ---------------------------------------------------------------------------
// 3) tf32 mma.sync GEMM with cp.async 4-stage ring  (R6 config, proven 16.7us)
//    CTA: 64m x 160n x K=512 (split over blockIdx.z). 256 thr, 8 warps.
//    Warp grid 2m x 4n, warp tile 32x40. Conflict-free LDS.32 fragment gathers.
//    grid (4, 8, 4) = 128 CTAs, one wave.
// ---------------------------------------------------------------------------
__device__ __forceinline__ void mma_tf32(float* c,
                                         float a0, float a1, float a2, float a3,
                                         float b0, float b1) {
    asm volatile(
        "mma.sync.aligned.m16n8k8.row.col.f32.tf32.tf32.f32 "
        "{%0,%1,%2,%3}, {%4,%5,%6,%7}, {%8,%9}, {%0,%1,%2,%3};"
        : "+f"(c[0]), "+f"(c[1]), "+f"(c[2]), "+f"(c[3])
        : "r"(__float_as_uint(a0)), "r"(__float_as_uint(a1)),
          "r"(__float_as_uint(a2)), "r"(__float_as_uint(a3)),
          "r"(__float_as_uint(b0)), "r"(__float_as_uint(b1)));
}

__global__ __launch_bounds__(256, 1) void gemm_mma_kernel() {
    extern __shared__ float sm[];
    const int tid = threadIdx.x, lane = tid & 31, wid = tid >> 5;
    const int wm = wid & 1;        // m warp (32 rows)
    const int wn = wid >> 1;       // n warp (40 cols)
    const int mBase = blockIdx.y * TM;
    const int nBase = blockIdx.x * TN;
    const size_t kbase0 = (size_t)blockIdx.z * KC;

    // ---- producer setup: 7 cp.async(16B) chunks per thread per stage ----
    size_t srcg[7];
    uint32_t dsts[7];
    const uint32_t sb = s2u(sm);
#pragma unroll
    for (int q = 0; q < 7; q++) {
        int c = tid + q * 256;                 // 0..1791
        const float* src;
        uint32_t d;
        if (c < 512) {                          // A: 64 rows x 8 chunks
            int r = c >> 3, p = c & 7;
            src = g_xr + (size_t)(mBase + r) * DD + kbase0 + p * 4;
            d = (uint32_t)(r * ROWP + p * 4) * 4;
        } else {                                // B: 160 rows x 8 chunks
            int cb = c - 512;
            int n = cb >> 3, p = cb & 7;
            src = g_bt + (size_t)(nBase + n) * DD + kbase0 + p * 4;
            d = (uint32_t)(B_OFF + n * ROWP + p * 4) * 4;
        }
        srcg[q] = __cvta_generic_to_global(src);
        dsts[q] = sb + d;
    }

#define LOAD_STAGE(it_) do {                                               \
    uint32_t soff_ = (uint32_t)(((it_) & 3) * (STG_FLOATS * 4));           \
    size_t go_ = (size_t)(it_) * 128;                                      \
    _Pragma("unroll")                                                      \
    for (int q_ = 0; q_ < 7; q_++)                                         \
        asm volatile("cp.async.cg.shared.global [%0], [%1], 16;"           \
                     :: "r"(dsts[q_] + soff_), "l"(srcg[q_] + go_));       \
    asm volatile("cp.async.commit_group;" ::: "memory");                   \
} while (0)

    // prologue: stages 0..2
    LOAD_STAGE(0);
    LOAD_STAGE(1);
    LOAD_STAGE(2);

    float acc[5][2][4] = {};
    const int aRow = wm * 32 + (lane >> 2);
    const int kCol = lane & 3;
    const int bRow = wn * 40 + (lane >> 2);

    const int NIT = KC / 32;   // 16
#pragma unroll 1
    for (int it = 0; it < NIT; ++it) {
        asm volatile("cp.async.wait_group 2;" ::: "memory");
        __syncthreads();
        const float* s = sm + (it & 3) * STG_FLOATS;

#pragma unroll
        for (int ks = 0; ks < 4; ++ks) {
            float a[2][4];
#pragma unroll
            for (int ms = 0; ms < 2; ++ms) {
                const float* ap = s + (aRow + ms * 16) * ROWP + ks * 8 + kCol;
                a[ms][0] = ap[0];
                a[ms][1] = ap[8 * ROWP];
                a[ms][2] = ap[4];
                a[ms][3] = ap[8 * ROWP + 4];
            }
#pragma unroll
            for (int nb = 0; nb < 5; ++nb) {
                const float* bp = s + B_OFF + (bRow + nb * 8) * ROWP + ks * 8 + kCol;
                float b0 = bp[0], b1 = bp[4];
                mma_tf32(acc[nb][0], a[0][0], a[0][1], a[0][2], a[0][3], b0, b1);
                mma_tf32(acc[nb][1], a[1][0], a[1][1], a[1][2], a[1][3], b0, b1);
            }
        }
        __syncthreads();
        if (it + 3 < NIT) LOAD_STAGE(it + 3);
        else asm volatile("cp.async.commit_group;" ::: "memory");
    }

    // ---- epilogue: write K-split partials ----
    float* op = g_part + (size_t)blockIdx.z * BB * NN;
    const int row0 = mBase + wm * 32 + (lane >> 2);
    const int col0 = nBase + wn * 40 + (lane & 3) * 2;
#pragma unroll
    for (int nb = 0; nb < 5; ++nb) {
#pragma unroll
        for (int ms = 0; ms < 2; ++ms) {
            int row = row0 + ms * 16;
            int col = col0 + nb * 8;
            *(float2*)&op[(size_t)row * NN + col] =
                make_float2(acc[nb][ms][0], acc[nb][ms][1]);
            *(float2*)&op[(size_t)(row + 8) * NN + col] =
                make_float2(acc[nb][ms][2], acc[nb][ms][3]);
        }
    }
#undef LOAD_STAGE
}

// ---------------------------------------------------------------------------
// 4) pairwise, min-trick (R6 structure, one kernel, direct out write):
//    sum_p |a_i - a_j| = Si + Sj - 2M,  M = sum_p min(a_ip, a_jp)
//    f = exp2(-Si) * sum_j exp2(2M - Sj) - 1 + bias
//    smem stores 2a (so the min-sum directly yields 2M) and Sj.
//    5 FMNMX go to the alu pipe; fma-pipe ops per pair drop 10 -> 5.
// ---------------------------------------------------------------------------
__global__ __launch_bounds__(512, 1)
void pairwise_kernel(const float* __restrict__ bias, float* __restrict__ out) {
    int k = blockIdx.x;
    int i = threadIdx.x;
    __shared__ float sD[BB][8];    // 2a0..2a4, Sj

    float a0 = 0.f, a1 = 0.f, a2 = 0.f, a3 = 0.f, a4 = 0.f;
#pragma unroll
    for (int s = 0; s < SPLIT; s++) {
        const float* p = g_part + (size_t)s * BB * NN + (size_t)i * NN + k * PP;
        a0 += p[0]; a1 += p[1]; a2 += p[2]; a3 += p[3]; a4 += p[4];
    }
    float Si = ((a0 + a1) + (a2 + a3)) + a4;
    float d0 = a0 + a0, d1 = a1 + a1, d2 = a2 + a2, d3 = a3 + a3, d4 = a4 + a4;
    sD[i][0] = d0; sD[i][1] = d1; sD[i][2] = d2; sD[i][3] = d3;
    sD[i][4] = d4; sD[i][5] = Si;
    __syncthreads();

    float acc = 0.f;
#pragma unroll 8
    for (int j = 0; j < BB; j++) {
        float4 v = *(const float4*)&sD[j][0];     // 2a0..2a3
        float2 w = *(const float2*)&sD[j][4];     // 2a4, Sj
        float m0 = fminf(d0, v.x);
        float m1 = fminf(d1, v.y);
        float m2 = fminf(d2, v.z);
        float m3 = fminf(d3, v.w);
        float m4 = fminf(d4, w.x);
        float arg = ((m0 + m1) + (m2 + m3)) + (m4 - w.y);   // 2M - Sj
        float e;
        asm("ex2.approx.ftz.f32 %0, %1;" : "=f"(e) : "f"(arg));
        acc += e;
    }
    float sc;
    asm("ex2.approx.ftz.f32 %0, %1;" : "=f"(sc) : "f"(-Si));
    out[(size_t)i * OUTW + DD + k] = fmaf(acc, sc, bias[k] - 1.0f);
}

// ---------------------------------------------------------------------------
extern "C" void kernel_launch(void* const* d_in, const int* in_sizes, int n_in,
                              void* d_out, int out_size) {
    const float* x     = (const float*)d_in[0];   // [512, 2048]
    const float* theta = (const float*)d_in[1];   // [2048, 128, 5]
    const float* lws   = (const float*)d_in[2];   // [128, 5]
    const float* bias  = (const float*)d_in[3];   // [128]
    float* out = (float*)d_out;                   // [512, 2176]

    cudaFuncSetAttribute(gemm_mma_kernel,
                         cudaFuncAttributeMaxDynamicSharedMemorySize, GEMM_SMEM);

    scale_kernel<<<20, 256>>>(theta, lws);
    round_x_kernel<<<256, 256>>>(x, out);
    transpose_kernel<<<dim3(NN / 32, DD / 32), dim3(32, 8)>>>(theta);
    gemm_mma_kernel<<<dim3(NN / TN, BB / TM, SPLIT), 256, GEMM_SMEM>>>();
    pairwise_kernel<<<KK, BB>>>(bias, out);
}

// round 11
// speedup vs baseline: 1.2554x; 1.0986x over previous
#include <cuda_runtime.h>
#include <cstdint>
#include <math.h>

#define BB 512
#define DD 2048
#define KK 128
#define PP 5
#define NN (KK * PP)      // 640
#define OUTW (DD + KK)    // 2176

#define SPLIT 4
#define KC (DD / SPLIT)   // 512 K per CTA
#define TM 64
#define TN 160
#define ROWP 36           // padded row stride (floats): conflict-free LDS.32 + 16B-aligned
#define B_OFF (TM * ROWP)             // 2304 floats
#define STG_FLOATS ((TM + TN) * ROWP) // 8064 floats = 32256 B
#define NSTAGE 4
#define GEMM_SMEM (NSTAGE * STG_FLOATS * 4)  // 129024 B

// ---------------- scratch (no cudaMalloc allowed) ----------------
__device__ float g_part[SPLIT * BB * NN];  // K-split partial actv (unscaled)
__device__ float g_scale[NN];              // exp(lws)/||theta|| * log2(e)
__device__ float g_xr[BB * DD];            // x rounded to tf32 (rna)
__device__ float g_bt[NN * DD];            // theta^T rounded to tf32 (NO scale)

__device__ __forceinline__ float rna_tf32(float v) {
    uint32_t u;
    asm("cvt.rna.tf32.f32 %0, %1;" : "=r"(u) : "f"(v));
    return __uint_as_float(u);
}
__device__ __forceinline__ uint32_t s2u(const void* p) {
    uint32_t a;
    asm("{ .reg .u64 t; cvta.to.shared.u64 t, %1; cvt.u32.u64 %0, t; }"
        : "=r"(a) : "l"(p));
    return a;
}
#define EX2(d, a) asm("ex2.approx.ftz.f32 %0, %1;" : "=f"(d) : "f"(a))

// ---------------------------------------------------------------------------
// 1) fused prep kernel, 3 roles by blockIdx.x, 256 threads each:
//    [0,20):        scale[col] = exp(lws)/||theta[:,col]|| * log2(e)
//    [20,1300):     transpose: g_bt[n][d] = rna_tf32(theta[d][n])   (no scale)
//    [1300,1556):   g_xr = rna_tf32(x); out[:, :2048] = x  (raw copy)
// ---------------------------------------------------------------------------
#define PREP_SCALE_B 20
#define PREP_TRANS_B 1280
#define PREP_ROUND_B 256
#define PREP_BLOCKS (PREP_SCALE_B + PREP_TRANS_B + PREP_ROUND_B)

__global__ __launch_bounds__(256) void prep_kernel(const float* __restrict__ x,
                                                   const float* __restrict__ theta,
                                                   const float* __restrict__ lws,
                                                   float* __restrict__ out) {
    __shared__ float smem[32][33];
    const int bid = blockIdx.x;
    const int tid = threadIdx.x;

    if (bid < PREP_SCALE_B) {
        // ---- scale role ----
        int c = tid & 31;
        int q = tid >> 5;
        int col = bid * 32 + c;
        float s = 0.f;
        for (int d = q; d < DD; d += 8) {
            float v = theta[(size_t)d * NN + col];
            s += v * v;
        }
        smem[q][c] = s;
        __syncthreads();
        if (q == 0) {
            float t = 0.f;
#pragma unroll
            for (int i = 0; i < 8; i++) t += smem[i][c];
            g_scale[col] = __expf(lws[col]) * rsqrtf(t) * 1.4426950408889634f;
        }
    } else if (bid < PREP_SCALE_B + PREP_TRANS_B) {
        // ---- transpose role ----
        int bt = bid - PREP_SCALE_B;
        int n0 = (bt % 20) * 32;
        int d0 = (bt / 20) * 32;
        int tx = tid & 31, ty = tid >> 5;
#pragma unroll
        for (int i = 0; i < 4; i++) {
            int r = ty + i * 8;
            smem[r][tx] = theta[(size_t)(d0 + r) * NN + n0 + tx];
        }
        __syncthreads();
#pragma unroll
        for (int i = 0; i < 4; i++) {
            int r = ty + i * 8;
            g_bt[(size_t)(n0 + r) * DD + d0 + tx] = rna_tf32(smem[tx][r]);
        }
    } else {
        // ---- round_x + copy role ----
        int bR = bid - PREP_SCALE_B - PREP_TRANS_B;    // 0..255
        const float4* xi = (const float4*)x;
        float4* xo = (float4*)g_xr;
        int n4 = BB * DD / 4;
        for (int i = bR * 256 + tid; i < n4; i += PREP_ROUND_B * 256) {
            float4 v = xi[i];
            int row = i >> 9;
            int c4 = i & 511;
            *(float4*)&out[(size_t)row * OUTW + c4 * 4] = v;
            v.x = rna_tf32(v.x); v.y = rna_tf32(v.y);
            v.z = rna_tf32(v.z); v.w = rna_tf32(v.w);
            xo[i] = v;
        }
    }
}

// ---------------------------------------------------------------------------
// 2) tf32 mma.sync GEMM with cp.async 4-stage ring  (frozen R9 config, 17.2us)
// ---------------------------------------------------------------------------
__device__ __forceinline__ void mma_tf32(float* c,
                                         float a0, float a1, float a2, float a3,
                                         float b0, float b1) {
    asm volatile(
        "mma.sync.aligned.m16n8k8.row.col.f32.tf32.tf32.f32 "
        "{%0,%1,%2,%3}, {%4,%5,%6,%7}, {%8,%9}, {%0,%1,%2,%3};"
        : "+f"(c[0]), "+f"(c[1]), "+f"(c[2]), "+f"(c[3])
        : "r"(__float_as_uint(a0)), "r"(__float_as_uint(a1)),
          "r"(__float_as_uint(a2)), "r"(__float_as_uint(a3)),
          "r"(__float_as_uint(b0)), "r"(__float_as_uint(b1)));
}

__global__ __launch_bounds__(256, 1) void gemm_mma_kernel() {
    extern __shared__ float sm[];
    const int tid = threadIdx.x, lane = tid & 31, wid = tid >> 5;
    const int wm = wid & 1;
    const int wn = wid >> 1;
    const int mBase = blockIdx.y * TM;
    const int nBase = blockIdx.x * TN;
    const size_t kbase0 = (size_t)blockIdx.z * KC;

    size_t srcg[7];
    uint32_t dsts[7];
    const uint32_t sb = s2u(sm);
#pragma unroll
    for (int q = 0; q < 7; q++) {
        int c = tid + q * 256;
        const float* src;
        uint32_t d;
        if (c < 512) {
            int r = c >> 3, p = c & 7;
            src = g_xr + (size_t)(mBase + r) * DD + kbase0 + p * 4;
            d = (uint32_t)(r * ROWP + p * 4) * 4;
        } else {
            int cb = c - 512;
            int n = cb >> 3, p = cb & 7;
            src = g_bt + (size_t)(nBase + n) * DD + kbase0 + p * 4;
            d = (uint32_t)(B_OFF + n * ROWP + p * 4) * 4;
        }
        srcg[q] = __cvta_generic_to_global(src);
        dsts[q] = sb + d;
    }

#define LOAD_STAGE(it_) do {                                               \
    uint32_t soff_ = (uint32_t)(((it_) & 3) * (STG_FLOATS * 4));           \
    size_t go_ = (size_t)(it_) * 128;                                      \
    _Pragma("unroll")                                                      \
    for (int q_ = 0; q_ < 7; q_++)                                         \
        asm volatile("cp.async.cg.shared.global [%0], [%1], 16;"           \
                     :: "r"(dsts[q_] + soff_), "l"(srcg[q_] + go_));       \
    asm volatile("cp.async.commit_group;" ::: "memory");                   \
} while (0)

    LOAD_STAGE(0);
    LOAD_STAGE(1);
    LOAD_STAGE(2);

    float acc[5][2][4] = {};
    const int aRow = wm * 32 + (lane >> 2);
    const int kCol = lane & 3;
    const int bRow = wn * 40 + (lane >> 2);

    const int NIT = KC / 32;   // 16
#pragma unroll 1
    for (int it = 0; it < NIT; ++it) {
        asm volatile("cp.async.wait_group 2;" ::: "memory");
        __syncthreads();
        const float* s = sm + (it & 3) * STG_FLOATS;

#pragma unroll
        for (int ks = 0; ks < 4; ++ks) {
            float a[2][4];
#pragma unroll
            for (int ms = 0; ms < 2; ++ms) {
                const float* ap = s + (aRow + ms * 16) * ROWP + ks * 8 + kCol;
                a[ms][0] = ap[0];
                a[ms][1] = ap[8 * ROWP];
                a[ms][2] = ap[4];
                a[ms][3] = ap[8 * ROWP + 4];
            }
#pragma unroll
            for (int nb = 0; nb < 5; ++nb) {
                const float* bp = s + B_OFF + (bRow + nb * 8) * ROWP + ks * 8 + kCol;
                float b0 = bp[0], b1 = bp[4];
                mma_tf32(acc[nb][0], a[0][0], a[0][1], a[0][2], a[0][3], b0, b1);
                mma_tf32(acc[nb][1], a[1][0], a[1][1], a[1][2], a[1][3], b0, b1);
            }
        }
        __syncthreads();
        if (it + 3 < NIT) LOAD_STAGE(it + 3);
        else asm volatile("cp.async.commit_group;" ::: "memory");
    }

    float* op = g_part + (size_t)blockIdx.z * BB * NN;
    const int row0 = mBase + wm * 32 + (lane >> 2);
    const int col0 = nBase + wn * 40 + (lane & 3) * 2;
#pragma unroll
    for (int nb = 0; nb < 5; ++nb) {
#pragma unroll
        for (int ms = 0; ms < 2; ++ms) {
            int row = row0 + ms * 16;
            int col = col0 + nb * 8;
            *(float2*)&op[(size_t)row * NN + col] =
                make_float2(acc[nb][ms][0], acc[nb][ms][1]);
            *(float2*)&op[(size_t)(row + 8) * NN + col] =
                make_float2(acc[nb][ms][2], acc[nb][ms][3]);
        }
    }
#undef LOAD_STAGE
}

// ---------------------------------------------------------------------------
// 3) pairwise, scalar min-trick (proven R9 mainloop), scale applied in setup:
//    sum_p |a_i - a_j| = Si + Sj - 2M,  M = sum_p min(a_ip, a_jp)
//    f = exp2(-Si) * sum_j exp2(2M - Sj) - 1 + bias
// ---------------------------------------------------------------------------
__global__ __launch_bounds__(512, 1)
void pairwise_kernel(const float* __restrict__ bias, float* __restrict__ out) {
    int k = blockIdx.x;
    int i = threadIdx.x;
    __shared__ float sD[BB][8];    // 2a0..2a4, Sj

    float a0, a1, a2, a3, a4;
    {
        float s0 = 0.f, s1 = 0.f, s2 = 0.f, s3 = 0.f, s4 = 0.f;
#pragma unroll
        for (int s = 0; s < SPLIT; s++) {
            const float* p = g_part + (size_t)s * BB * NN + (size_t)i * NN + k * PP;
            s0 += p[0]; s1 += p[1]; s2 += p[2]; s3 += p[3]; s4 += p[4];
        }
        const float* sc = g_scale + k * PP;
        a0 = s0 * sc[0]; a1 = s1 * sc[1]; a2 = s2 * sc[2];
        a3 = s3 * sc[3]; a4 = s4 * sc[4];
    }
    float Si = ((a0 + a1) + (a2 + a3)) + a4;
    float d0 = a0 + a0, d1 = a1 + a1, d2 = a2 + a2, d3 = a3 + a3, d4 = a4 + a4;
    sD[i][0] = d0; sD[i][1] = d1; sD[i][2] = d2; sD[i][3] = d3;
    sD[i][4] = d4; sD[i][5] = Si;
    __syncthreads();

    float acc = 0.f;
#pragma unroll 8
    for (int j = 0; j < BB; j++) {
        float4 v = *(const float4*)&sD[j][0];     // 2a0..2a3
        float2 w = *(const float2*)&sD[j][4];     // 2a4, Sj
        float m0 = fminf(d0, v.x);
        float m1 = fminf(d1, v.y);
        float m2 = fminf(d2, v.z);
        float m3 = fminf(d3, v.w);
        float m4 = fminf(d4, w.x);
        float arg = ((m0 + m1) + (m2 + m3)) + (m4 - w.y);   // 2M - Sj
        float e;
        EX2(e, arg);
        acc += e;
    }
    float sc;
    EX2(sc, -Si);
    out[(size_t)i * OUTW + DD + k] = fmaf(acc, sc, bias[k] - 1.0f);
}

// ---------------------------------------------------------------------------
extern "C" void kernel_launch(void* const* d_in, const int* in_sizes, int n_in,
                              void* d_out, int out_size) {
    const float* x     = (const float*)d_in[0];   // [512, 2048]
    const float* theta = (const float*)d_in[1];   // [2048, 128, 5]
    const float* lws   = (const float*)d_in[2];   // [128, 5]
    const float* bias  = (const float*)d_in[3];   // [128]
    float* out = (float*)d_out;                   // [512, 2176]

    cudaFuncSetAttribute(gemm_mma_kernel,
                         cudaFuncAttributeMaxDynamicSharedMemorySize, GEMM_SMEM);

    prep_kernel<<<PREP_BLOCKS, 256>>>(x, theta, lws, out);
    gemm_mma_kernel<<<dim3(NN / TN, BB / TM, SPLIT), 256, GEMM_SMEM>>>();
    pairwise_kernel<<<KK, BB>>>(bias, out);
}